// round 15
// baseline (speedup 1.0000x reference)
#include <cuda_runtime.h>

#define N_NODES 200000
#define N_VAR   112000
#define N_EDGES 3200000
#define HID     64
#define CAP     64      // max in-degree bucket (Poisson(16): P(deg>64) ~ 1e-18)
#define PAD     76      // smem row stride: 304B, 16B-aligned

// ---- scratch: __device__ globals (referenced ONLY from device code) ----
__device__ int    d_cnt[N_NODES];
__device__ int    d_col[(size_t)N_NODES * CAP];
__device__ float  d_dinv[N_NODES];
__device__ float2 d_pg[N_NODES];                     // x[n] * dinv[n]
__device__ float4 d_A1d[N_NODES];                    // (A1.x, A1.y, dinv, 0) per node
__device__ float  d_Wc[HID * HID + HID];             // W2@Wfc, then bc = b2@Wfc+bfc

// bucket edges by destination: 2 edges/thread, one int atomic each
__global__ void k_fill(const int* __restrict__ ei) {
    int t = blockIdx.x * blockDim.x + threadIdx.x;
    if (t >= N_EDGES / 2) return;
    int2 s2 = ((const int2*)ei)[t];
    int2 d2 = ((const int2*)(ei + N_EDGES))[t];
    int p0 = atomicAdd(&d_cnt[d2.x], 1);
    if (p0 < CAP) d_col[d2.x * CAP + p0] = s2.x;
    int p1 = atomicAdd(&d_cnt[d2.y], 1);
    if (p1 < CAP) d_col[d2.y * CAP + p1] = s2.y;
}

// precompute Wc = W2 @ Wfc and bc = b2 @ Wfc + bfc
__global__ void k_wc(const float* __restrict__ W2, const float* __restrict__ b2,
                     const float* __restrict__ Wfc, const float* __restrict__ bfc) {
    int t = blockIdx.x * blockDim.x + threadIdx.x;
    if (t < HID * HID) {
        int k = t >> 6, c = t & 63;
        float o = 0.0f;
#pragma unroll 16
        for (int j = 0; j < HID; j++) o += W2[k * HID + j] * Wfc[j * HID + c];
        d_Wc[t] = o;
    } else if (t < HID * HID + HID) {
        int c = t - HID * HID;
        float o = bfc[c];
#pragma unroll 16
        for (int j = 0; j < HID; j++) o += b2[j] * Wfc[j * HID + c];
        d_Wc[HID * HID + c] = o;
    }
}

// per node: dinv and pg = x * dinv
__global__ void k_prep(const float2* __restrict__ x) {
    int n = blockIdx.x * blockDim.x + threadIdx.x;
    if (n >= N_NODES) return;
    float di = rsqrtf((float)d_cnt[n] + 1.0f);
    d_dinv[n] = di;
    float2 xv = __ldg(&x[n]);
    d_pg[n] = make_float2(xv.x * di, xv.y * di);
}

// layer-1 aggregation, ONE WARP PER NODE with warp-uniform gathers:
// every lane loads the same pg[src] (broadcast, 1 wavefront/edge) and
// accumulates redundantly; lane 0 stores. A1 = dinv*(sum pg[src] + pg[n]).
__global__ void __launch_bounds__(256) k_agg1() {
    int warp = threadIdx.x >> 5, lane = threadIdx.x & 31;
    int n = blockIdx.x * 8 + warp;            // 25000 blocks * 8 == N_NODES exact
    int deg = d_cnt[n];
    if (deg > CAP) deg = CAP;
    const int* cl = &d_col[n * CAP];
    float ax = 0.0f, ay = 0.0f;
    int e = 0;
    for (; e + 8 <= deg; e += 8) {            // 8 uniform 8B loads in flight
        int s0 = cl[e],     s1 = cl[e + 1], s2 = cl[e + 2], s3 = cl[e + 3];
        int s4 = cl[e + 4], s5 = cl[e + 5], s6 = cl[e + 6], s7 = cl[e + 7];
        float2 p0 = d_pg[s0], p1 = d_pg[s1], p2 = d_pg[s2], p3 = d_pg[s3];
        float2 p4 = d_pg[s4], p5 = d_pg[s5], p6 = d_pg[s6], p7 = d_pg[s7];
        ax += ((p0.x + p1.x) + (p2.x + p3.x)) + ((p4.x + p5.x) + (p6.x + p7.x));
        ay += ((p0.y + p1.y) + (p2.y + p3.y)) + ((p4.y + p5.y) + (p6.y + p7.y));
    }
    for (; e < deg; e++) {
        float2 p = d_pg[cl[e]];
        ax += p.x; ay += p.y;
    }
    float di = d_dinv[n];
    float2 pn = d_pg[n];
    if (lane == 0)
        d_A1d[n] = make_float4(di * (ax + pn.x), di * (ay + pn.y), di, 0.0f);
}

// layer-2: gather (A1,dinv) 16B/edge (L2-resident), reconstruct g1 columns
// on the fly, aggregate, then fused 4x4-register-tiled matmul.
__global__ void __launch_bounds__(256) k_agg2(float* __restrict__ out,
                                              const float* __restrict__ W1,
                                              const float* __restrict__ b1) {
    __shared__ float sWT[HID][PAD];  // transposed Wc
    __shared__ float sR[64][PAD];    // aggregated rows; reused for outputs
    __shared__ float sBc[HID];

    int tid = threadIdx.x;           // 256 threads, 8 warps, 64 nodes/block
    for (int i = tid; i < HID * HID; i += 256) {
        int k = i >> 6, c = i & 63;
        sWT[c][k] = d_Wc[i];
    }
    if (tid < HID) sBc[tid] = d_Wc[HID * HID + tid];

    int warp = tid >> 5, lane = tid & 31;

    // per-lane W1/b1 for columns (lane) and (lane+32)
    float w0a = __ldg(&W1[lane]),      w0b = __ldg(&W1[lane + 32]);
    float w1a = __ldg(&W1[64 + lane]), w1b = __ldg(&W1[96 + lane]);
    float bA  = __ldg(&b1[lane]),      bB  = __ldg(&b1[lane + 32]);

    const float4* __restrict__ A1d = d_A1d;

#pragma unroll
    for (int rep = 0; rep < 8; rep++) {
        int nl = warp * 8 + rep;                 // 0..63
        int n  = blockIdx.x * 64 + nl;
        int deg = d_cnt[n];
        if (deg > CAP) deg = CAP;
        const int* cl = &d_col[n * CAP];
        float a0 = 0.0f, a1 = 0.0f;
        int e = 0;
        for (; e + 8 <= deg; e += 8) {
            // 8 warp-uniform 16B loads in flight (L2-resident 3.2MB table)
            int s0 = cl[e],     s1 = cl[e + 1], s2 = cl[e + 2], s3 = cl[e + 3];
            int s4 = cl[e + 4], s5 = cl[e + 5], s6 = cl[e + 6], s7 = cl[e + 7];
            float4 q0 = A1d[s0];
            float4 q1 = A1d[s1];
            float4 q2 = A1d[s2];
            float4 q3 = A1d[s3];
            float4 q4 = A1d[s4];
            float4 q5 = A1d[s5];
            float4 q6 = A1d[s6];
            float4 q7 = A1d[s7];
            a0 += fmaxf(q0.x * w0a + q0.y * w1a + bA, 0.0f) * q0.z;
            a1 += fmaxf(q0.x * w0b + q0.y * w1b + bB, 0.0f) * q0.z;
            a0 += fmaxf(q1.x * w0a + q1.y * w1a + bA, 0.0f) * q1.z;
            a1 += fmaxf(q1.x * w0b + q1.y * w1b + bB, 0.0f) * q1.z;
            a0 += fmaxf(q2.x * w0a + q2.y * w1a + bA, 0.0f) * q2.z;
            a1 += fmaxf(q2.x * w0b + q2.y * w1b + bB, 0.0f) * q2.z;
            a0 += fmaxf(q3.x * w0a + q3.y * w1a + bA, 0.0f) * q3.z;
            a1 += fmaxf(q3.x * w0b + q3.y * w1b + bB, 0.0f) * q3.z;
            a0 += fmaxf(q4.x * w0a + q4.y * w1a + bA, 0.0f) * q4.z;
            a1 += fmaxf(q4.x * w0b + q4.y * w1b + bB, 0.0f) * q4.z;
            a0 += fmaxf(q5.x * w0a + q5.y * w1a + bA, 0.0f) * q5.z;
            a1 += fmaxf(q5.x * w0b + q5.y * w1b + bB, 0.0f) * q5.z;
            a0 += fmaxf(q6.x * w0a + q6.y * w1a + bA, 0.0f) * q6.z;
            a1 += fmaxf(q6.x * w0b + q6.y * w1b + bB, 0.0f) * q6.z;
            a0 += fmaxf(q7.x * w0a + q7.y * w1a + bA, 0.0f) * q7.z;
            a1 += fmaxf(q7.x * w0b + q7.y * w1b + bB, 0.0f) * q7.z;
        }
        for (; e < deg; e++) {
            float4 q = A1d[cl[e]];
            a0 += fmaxf(q.x * w0a + q.y * w1a + bA, 0.0f) * q.z;
            a1 += fmaxf(q.x * w0b + q.y * w1b + bB, 0.0f) * q.z;
        }
        // self-loop: g1[n]
        float4 qn = A1d[n];
        a0 += fmaxf(qn.x * w0a + qn.y * w1a + bA, 0.0f) * qn.z;
        a1 += fmaxf(qn.x * w0b + qn.y * w1b + bB, 0.0f) * qn.z;
        float di = qn.z;
        sR[nl][lane]      = a0 * di;
        sR[nl][lane + 32] = a1 * di;
    }
    __syncthreads();

    // matmul 4x4: m0 = tid&15 -> nodes m0+16i; c0 = (tid>>4)*4 -> cols c0..c0+3
    int m0 = tid & 15, c0 = (tid >> 4) << 2;
    float o[4][4];
#pragma unroll
    for (int i = 0; i < 4; i++)
#pragma unroll
        for (int j = 0; j < 4; j++) o[i][j] = 0.0f;
#pragma unroll
    for (int k = 0; k < HID; k += 4) {
        float4 rr[4], ww[4];
        rr[0] = *(const float4*)&sR[m0][k];
        rr[1] = *(const float4*)&sR[m0 + 16][k];
        rr[2] = *(const float4*)&sR[m0 + 32][k];
        rr[3] = *(const float4*)&sR[m0 + 48][k];
        ww[0] = *(const float4*)&sWT[c0][k];
        ww[1] = *(const float4*)&sWT[c0 + 1][k];
        ww[2] = *(const float4*)&sWT[c0 + 2][k];
        ww[3] = *(const float4*)&sWT[c0 + 3][k];
#pragma unroll
        for (int i = 0; i < 4; i++)
#pragma unroll
            for (int j = 0; j < 4; j++)
                o[i][j] += rr[i].x * ww[j].x + rr[i].y * ww[j].y +
                           rr[i].z * ww[j].z + rr[i].w * ww[j].w;
    }
    float bb[4] = {sBc[c0], sBc[c0 + 1], sBc[c0 + 2], sBc[c0 + 3]};
    __syncthreads();                  // all reads of sR done -> safe to overwrite
#pragma unroll
    for (int i = 0; i < 4; i++) {
        float4 v;
        v.x = rintf(fmaxf(o[i][0] + bb[0], 0.0f));   // round-half-even == jnp.round
        v.y = rintf(fmaxf(o[i][1] + bb[1], 0.0f));
        v.z = rintf(fmaxf(o[i][2] + bb[2], 0.0f));
        v.w = rintf(fmaxf(o[i][3] + bb[3], 0.0f));
        *(float4*)&sR[m0 + 16 * i][c0] = v;
    }
    __syncthreads();

#pragma unroll
    for (int rep = 0; rep < 8; rep++) {
        int nl = warp * 8 + rep;
        size_t ob = ((size_t)blockIdx.x * 64 + nl) * HID;
        out[ob + lane]      = sR[nl][lane];
        out[ob + lane + 32] = sR[nl][lane + 32];
    }
}

extern "C" void kernel_launch(void* const* d_in, const int* in_sizes, int n_in,
                              void* d_out, int out_size) {
    const float* x   = (const float*)d_in[0];   // [200000, 2]
    const int*   ei  = (const int*)d_in[1];     // [2, 3200000]
    const float* W1  = (const float*)d_in[2];   // [2, 64]
    const float* b1  = (const float*)d_in[3];   // [64]
    const float* W2  = (const float*)d_in[4];   // [64, 64]
    const float* b2  = (const float*)d_in[5];   // [64]
    const float* Wfc = (const float*)d_in[6];   // [64, 64]
    const float* bfc = (const float*)d_in[7];   // [64]
    float* out = (float*)d_out;                 // [112000*64] flat

    void* cnt_addr = nullptr;
    cudaGetSymbolAddress(&cnt_addr, d_cnt);     // lookup only, no allocation
    cudaMemsetAsync(cnt_addr, 0, N_NODES * sizeof(int));

    k_wc<<<(HID * HID + HID + 255) / 256, 256>>>(W2, b2, Wfc, bfc);
    k_fill<<<(N_EDGES / 2 + 255) / 256, 256>>>(ei);
    k_prep<<<(N_NODES + 255) / 256, 256>>>((const float2*)x);
    k_agg1<<<N_NODES / 8, 256>>>();
    k_agg2<<<N_VAR / 64, 256>>>(out, W1, b1);
}

// round 16
// speedup vs baseline: 1.2261x; 1.2261x over previous
#include <cuda_runtime.h>

#define N_NODES 200000
#define N_VAR   112000
#define N_EDGES 3200000
#define HID     64
#define CAP     64      // max in-degree bucket (Poisson(16): P(deg>64) ~ 1e-18)
#define PAD     76      // smem row stride: 304B, 16B-aligned

// ---- scratch: __device__ globals (referenced ONLY from device code) ----
__device__ int    d_cnt[N_NODES];
__device__ int    d_col[(size_t)N_NODES * CAP];
__device__ float  d_dinv[N_NODES];
__device__ float2 d_pg[N_NODES];                     // x[n] * dinv[n]
__device__ float4 d_A1d[N_NODES];                    // (A1.x, A1.y, dinv, 0) per node
__device__ float  d_Wc[HID * HID + HID];             // W2@Wfc, then bc = b2@Wfc+bfc

// bucket edges by destination: 2 edges/thread, one int atomic each
__global__ void k_fill(const int* __restrict__ ei) {
    int t = blockIdx.x * blockDim.x + threadIdx.x;
    if (t >= N_EDGES / 2) return;
    int2 s2 = ((const int2*)ei)[t];
    int2 d2 = ((const int2*)(ei + N_EDGES))[t];
    int p0 = atomicAdd(&d_cnt[d2.x], 1);
    if (p0 < CAP) d_col[d2.x * CAP + p0] = s2.x;
    int p1 = atomicAdd(&d_cnt[d2.y], 1);
    if (p1 < CAP) d_col[d2.y * CAP + p1] = s2.y;
}

// precompute Wc = W2 @ Wfc and bc = b2 @ Wfc + bfc
__global__ void k_wc(const float* __restrict__ W2, const float* __restrict__ b2,
                     const float* __restrict__ Wfc, const float* __restrict__ bfc) {
    int t = blockIdx.x * blockDim.x + threadIdx.x;
    if (t < HID * HID) {
        int k = t >> 6, c = t & 63;
        float o = 0.0f;
#pragma unroll 16
        for (int j = 0; j < HID; j++) o += W2[k * HID + j] * Wfc[j * HID + c];
        d_Wc[t] = o;
    } else if (t < HID * HID + HID) {
        int c = t - HID * HID;
        float o = bfc[c];
#pragma unroll 16
        for (int j = 0; j < HID; j++) o += b2[j] * Wfc[j * HID + c];
        d_Wc[HID * HID + c] = o;
    }
}

// per node: dinv and pg = x * dinv
__global__ void k_prep(const float2* __restrict__ x) {
    int n = blockIdx.x * blockDim.x + threadIdx.x;
    if (n >= N_NODES) return;
    float di = rsqrtf((float)d_cnt[n] + 1.0f);
    d_dinv[n] = di;
    float2 xv = __ldg(&x[n]);
    d_pg[n] = make_float2(xv.x * di, xv.y * di);
}

// layer-1 aggregation: A1 = dinv*(sum pg[src] + pg[n]); 16 gathers in flight
// (R14 champion form — measured at its L1tex wavefront floor ~24us)
__global__ void k_agg1() {
    int n = blockIdx.x * blockDim.x + threadIdx.x;
    if (n >= N_NODES) return;
    int deg = d_cnt[n];
    if (deg > CAP) deg = CAP;
    const int* cl = &d_col[n * CAP];
    float ax = 0.0f, ay = 0.0f;
    int e = 0;
    for (; e + 16 <= deg; e += 16) {
        int4 i0 = *(const int4*)&cl[e];
        int4 i1 = *(const int4*)&cl[e + 4];
        int4 i2 = *(const int4*)&cl[e + 8];
        int4 i3 = *(const int4*)&cl[e + 12];
        float2 p0 = d_pg[i0.x], p1 = d_pg[i0.y], p2 = d_pg[i0.z], p3 = d_pg[i0.w];
        float2 p4 = d_pg[i1.x], p5 = d_pg[i1.y], p6 = d_pg[i1.z], p7 = d_pg[i1.w];
        float2 p8 = d_pg[i2.x], p9 = d_pg[i2.y], pa = d_pg[i2.z], pb = d_pg[i2.w];
        float2 pc = d_pg[i3.x], pd = d_pg[i3.y], pe = d_pg[i3.z], pf = d_pg[i3.w];
        ax += (((p0.x + p1.x) + (p2.x + p3.x)) + ((p4.x + p5.x) + (p6.x + p7.x)))
            + (((p8.x + p9.x) + (pa.x + pb.x)) + ((pc.x + pd.x) + (pe.x + pf.x)));
        ay += (((p0.y + p1.y) + (p2.y + p3.y)) + ((p4.y + p5.y) + (p6.y + p7.y)))
            + (((p8.y + p9.y) + (pa.y + pb.y)) + ((pc.y + pd.y) + (pe.y + pf.y)));
    }
    for (; e + 4 <= deg; e += 4) {
        int4 i0 = *(const int4*)&cl[e];
        float2 p0 = d_pg[i0.x], p1 = d_pg[i0.y], p2 = d_pg[i0.z], p3 = d_pg[i0.w];
        ax += (p0.x + p1.x) + (p2.x + p3.x);
        ay += (p0.y + p1.y) + (p2.y + p3.y);
    }
    for (; e < deg; e++) {
        float2 p = d_pg[cl[e]];
        ax += p.x; ay += p.y;
    }
    float di = d_dinv[n];
    float2 pn = d_pg[n];
    ax = di * (ax + pn.x);
    ay = di * (ay + pn.y);
    d_A1d[n] = make_float4(ax, ay, di, 0.0f);
}

// layer-2: gather (A1,dinv) 16B/edge (L2-resident), reconstruct g1 columns
// on the fly, aggregate, then fused 4x4-register-tiled matmul.
__global__ void __launch_bounds__(256) k_agg2(float* __restrict__ out,
                                              const float* __restrict__ W1,
                                              const float* __restrict__ b1) {
    __shared__ float sWT[HID][PAD];  // transposed Wc
    __shared__ float sR[64][PAD];    // aggregated rows; reused for outputs
    __shared__ float sBc[HID];

    int tid = threadIdx.x;           // 256 threads, 8 warps, 64 nodes/block
    for (int i = tid; i < HID * HID; i += 256) {
        int k = i >> 6, c = i & 63;
        sWT[c][k] = d_Wc[i];
    }
    if (tid < HID) sBc[tid] = d_Wc[HID * HID + tid];

    int warp = tid >> 5, lane = tid & 31;

    // per-lane W1/b1 for columns (lane) and (lane+32)
    float w0a = __ldg(&W1[lane]),      w0b = __ldg(&W1[lane + 32]);
    float w1a = __ldg(&W1[64 + lane]), w1b = __ldg(&W1[96 + lane]);
    float bA  = __ldg(&b1[lane]),      bB  = __ldg(&b1[lane + 32]);

    const float4* __restrict__ A1d = d_A1d;

#pragma unroll
    for (int rep = 0; rep < 8; rep++) {
        int nl = warp * 8 + rep;                 // 0..63
        int n  = blockIdx.x * 64 + nl;
        int deg = d_cnt[n];
        if (deg > CAP) deg = CAP;
        const int* cl = &d_col[n * CAP];
        float a0 = 0.0f, a1 = 0.0f;
        int e = 0;
        for (; e + 8 <= deg; e += 8) {
            // 8 warp-uniform 16B loads in flight (L2-resident 3.2MB table)
            int s0 = cl[e],     s1 = cl[e + 1], s2 = cl[e + 2], s3 = cl[e + 3];
            int s4 = cl[e + 4], s5 = cl[e + 5], s6 = cl[e + 6], s7 = cl[e + 7];
            float4 q0 = A1d[s0];
            float4 q1 = A1d[s1];
            float4 q2 = A1d[s2];
            float4 q3 = A1d[s3];
            float4 q4 = A1d[s4];
            float4 q5 = A1d[s5];
            float4 q6 = A1d[s6];
            float4 q7 = A1d[s7];
            a0 += fmaxf(q0.x * w0a + q0.y * w1a + bA, 0.0f) * q0.z;
            a1 += fmaxf(q0.x * w0b + q0.y * w1b + bB, 0.0f) * q0.z;
            a0 += fmaxf(q1.x * w0a + q1.y * w1a + bA, 0.0f) * q1.z;
            a1 += fmaxf(q1.x * w0b + q1.y * w1b + bB, 0.0f) * q1.z;
            a0 += fmaxf(q2.x * w0a + q2.y * w1a + bA, 0.0f) * q2.z;
            a1 += fmaxf(q2.x * w0b + q2.y * w1b + bB, 0.0f) * q2.z;
            a0 += fmaxf(q3.x * w0a + q3.y * w1a + bA, 0.0f) * q3.z;
            a1 += fmaxf(q3.x * w0b + q3.y * w1b + bB, 0.0f) * q3.z;
            a0 += fmaxf(q4.x * w0a + q4.y * w1a + bA, 0.0f) * q4.z;
            a1 += fmaxf(q4.x * w0b + q4.y * w1b + bB, 0.0f) * q4.z;
            a0 += fmaxf(q5.x * w0a + q5.y * w1a + bA, 0.0f) * q5.z;
            a1 += fmaxf(q5.x * w0b + q5.y * w1b + bB, 0.0f) * q5.z;
            a0 += fmaxf(q6.x * w0a + q6.y * w1a + bA, 0.0f) * q6.z;
            a1 += fmaxf(q6.x * w0b + q6.y * w1b + bB, 0.0f) * q6.z;
            a0 += fmaxf(q7.x * w0a + q7.y * w1a + bA, 0.0f) * q7.z;
            a1 += fmaxf(q7.x * w0b + q7.y * w1b + bB, 0.0f) * q7.z;
        }
        if (e + 4 <= deg) {
            // 4-wide middle step: one parallel round for deg%8 in [4,7]
            int s0 = cl[e], s1 = cl[e + 1], s2 = cl[e + 2], s3 = cl[e + 3];
            float4 q0 = A1d[s0];
            float4 q1 = A1d[s1];
            float4 q2 = A1d[s2];
            float4 q3 = A1d[s3];
            a0 += fmaxf(q0.x * w0a + q0.y * w1a + bA, 0.0f) * q0.z;
            a1 += fmaxf(q0.x * w0b + q0.y * w1b + bB, 0.0f) * q0.z;
            a0 += fmaxf(q1.x * w0a + q1.y * w1a + bA, 0.0f) * q1.z;
            a1 += fmaxf(q1.x * w0b + q1.y * w1b + bB, 0.0f) * q1.z;
            a0 += fmaxf(q2.x * w0a + q2.y * w1a + bA, 0.0f) * q2.z;
            a1 += fmaxf(q2.x * w0b + q2.y * w1b + bB, 0.0f) * q2.z;
            a0 += fmaxf(q3.x * w0a + q3.y * w1a + bA, 0.0f) * q3.z;
            a1 += fmaxf(q3.x * w0b + q3.y * w1b + bB, 0.0f) * q3.z;
            e += 4;
        }
        for (; e < deg; e++) {
            float4 q = A1d[cl[e]];
            a0 += fmaxf(q.x * w0a + q.y * w1a + bA, 0.0f) * q.z;
            a1 += fmaxf(q.x * w0b + q.y * w1b + bB, 0.0f) * q.z;
        }
        // self-loop: g1[n]
        float4 qn = A1d[n];
        a0 += fmaxf(qn.x * w0a + qn.y * w1a + bA, 0.0f) * qn.z;
        a1 += fmaxf(qn.x * w0b + qn.y * w1b + bB, 0.0f) * qn.z;
        float di = qn.z;
        sR[nl][lane]      = a0 * di;
        sR[nl][lane + 32] = a1 * di;
    }
    __syncthreads();

    // matmul 4x4: m0 = tid&15 -> nodes m0+16i; c0 = (tid>>4)*4 -> cols c0..c0+3
    int m0 = tid & 15, c0 = (tid >> 4) << 2;
    float o[4][4];
#pragma unroll
    for (int i = 0; i < 4; i++)
#pragma unroll
        for (int j = 0; j < 4; j++) o[i][j] = 0.0f;
#pragma unroll
    for (int k = 0; k < HID; k += 4) {
        float4 rr[4], ww[4];
        rr[0] = *(const float4*)&sR[m0][k];
        rr[1] = *(const float4*)&sR[m0 + 16][k];
        rr[2] = *(const float4*)&sR[m0 + 32][k];
        rr[3] = *(const float4*)&sR[m0 + 48][k];
        ww[0] = *(const float4*)&sWT[c0][k];
        ww[1] = *(const float4*)&sWT[c0 + 1][k];
        ww[2] = *(const float4*)&sWT[c0 + 2][k];
        ww[3] = *(const float4*)&sWT[c0 + 3][k];
#pragma unroll
        for (int i = 0; i < 4; i++)
#pragma unroll
            for (int j = 0; j < 4; j++)
                o[i][j] += rr[i].x * ww[j].x + rr[i].y * ww[j].y +
                           rr[i].z * ww[j].z + rr[i].w * ww[j].w;
    }
    float bb[4] = {sBc[c0], sBc[c0 + 1], sBc[c0 + 2], sBc[c0 + 3]};
    __syncthreads();                  // all reads of sR done -> safe to overwrite
#pragma unroll
    for (int i = 0; i < 4; i++) {
        float4 v;
        v.x = rintf(fmaxf(o[i][0] + bb[0], 0.0f));   // round-half-even == jnp.round
        v.y = rintf(fmaxf(o[i][1] + bb[1], 0.0f));
        v.z = rintf(fmaxf(o[i][2] + bb[2], 0.0f));
        v.w = rintf(fmaxf(o[i][3] + bb[3], 0.0f));
        *(float4*)&sR[m0 + 16 * i][c0] = v;
    }
    __syncthreads();

#pragma unroll
    for (int rep = 0; rep < 8; rep++) {
        int nl = warp * 8 + rep;
        size_t ob = ((size_t)blockIdx.x * 64 + nl) * HID;
        out[ob + lane]      = sR[nl][lane];
        out[ob + lane + 32] = sR[nl][lane + 32];
    }
}

extern "C" void kernel_launch(void* const* d_in, const int* in_sizes, int n_in,
                              void* d_out, int out_size) {
    const float* x   = (const float*)d_in[0];   // [200000, 2]
    const int*   ei  = (const int*)d_in[1];     // [2, 3200000]
    const float* W1  = (const float*)d_in[2];   // [2, 64]
    const float* b1  = (const float*)d_in[3];   // [64]
    const float* W2  = (const float*)d_in[4];   // [64, 64]
    const float* b2  = (const float*)d_in[5];   // [64]
    const float* Wfc = (const float*)d_in[6];   // [64, 64]
    const float* bfc = (const float*)d_in[7];   // [64]
    float* out = (float*)d_out;                 // [112000*64] flat

    void* cnt_addr = nullptr;
    cudaGetSymbolAddress(&cnt_addr, d_cnt);     // lookup only, no allocation
    cudaMemsetAsync(cnt_addr, 0, N_NODES * sizeof(int));

    k_wc<<<(HID * HID + HID + 255) / 256, 256>>>(W2, b2, Wfc, bfc);
    k_fill<<<(N_EDGES / 2 + 255) / 256, 256>>>(ei);
    k_prep<<<(N_NODES + 255) / 256, 256>>>((const float2*)x);
    k_agg1<<<(N_NODES + 255) / 256, 256>>>();
    k_agg2<<<N_VAR / 64, 256>>>(out, W1, b1);
}